// round 2
// baseline (speedup 1.0000x reference)
#include <cuda_runtime.h>
#include <math.h>
#include <float.h>

// ---------------------------------------------------------------------------
// VQ-VAE quantizer:
//   f_emb    [N=65536, D=256] fp32
//   codebook [K=1024,  D=256] fp32
// Outputs concatenated in d_out (float32):
//   [0, N*D)          quantized = f + (cb[idx] - f)   (straight-through value)
//   [N*D]             perplexity
//   [N*D+1, N*D+1+N)  encoding indices (as float)
// ---------------------------------------------------------------------------

#define D       256
#define D4      (D / 4)
#define TM      64          // rows per CTA
#define TK      64          // codebook chunk per stage
#define STRIDE  257         // smem row stride (floats): 257 % 32 == 1 -> conflict-free
#define NMAX    65536
#define KMAX    1024

__device__ int   g_idx[NMAX];
__device__ float g_sx[NMAX];
__device__ float g_se[KMAX];
__device__ int   g_hist[KMAX];

// ---------------------------------------------------------------------------
__global__ void zero_hist_kernel(int K) {
    int k = blockIdx.x * blockDim.x + threadIdx.x;
    if (k < K) g_hist[k] = 0;
}

// Row sum-of-squares. which==0 -> g_sx, which==1 -> g_se. One warp per row.
__global__ void rownorm_kernel(const float* __restrict__ v, int nrows, int which) {
    int warp = (blockIdx.x * blockDim.x + threadIdx.x) >> 5;
    int lane = threadIdx.x & 31;
    if (warp >= nrows) return;
    const float4* v4 = reinterpret_cast<const float4*>(v) + (long)warp * D4;
    float s = 0.0f;
#pragma unroll
    for (int i = 0; i < D4 / 32; i++) {
        float4 a = v4[lane + 32 * i];
        s += a.x * a.x + a.y * a.y + a.z * a.z + a.w * a.w;
    }
#pragma unroll
    for (int o = 16; o > 0; o >>= 1) s += __shfl_xor_sync(0xFFFFFFFFu, s, o);
    if (lane == 0) {
        if (which == 0) g_sx[warp] = s;
        else            g_se[warp] = s;
    }
}

// ---------------------------------------------------------------------------
// Fused distance + argmin.  d = fl(fl(s_x + s_e) - 2*dot)  (replicates reference
// fp32 rounding structure; ties broken by lowest index like jnp.argmin).
// 256 threads: warp w handles rows w*8..w*8+7; lane covers codes {lane+32j}
// within a TK=64 chunk (j = 0..1).
// ---------------------------------------------------------------------------
extern __shared__ float dyn_smem[];

__global__ __launch_bounds__(256, 1)
void argmin_kernel(const float* __restrict__ f, const float* __restrict__ cb, int K) {
    float* xs = dyn_smem;                 // [TM][STRIDE]
    float* es = dyn_smem + TM * STRIDE;   // [TK][STRIDE]

    const int tid  = threadIdx.x;
    const int w    = tid >> 5;
    const int lane = tid & 31;
    const long rb  = (long)blockIdx.x * TM;

    // Stage x tile (rows rb..rb+63)
    const float4* f4 = reinterpret_cast<const float4*>(f);
    for (int i = tid; i < TM * D4; i += 256) {
        int r = i >> 6, d4 = i & 63;
        float4 v = f4[(rb + r) * D4 + d4];
        float* p = xs + r * STRIDE + d4 * 4;
        p[0] = v.x; p[1] = v.y; p[2] = v.z; p[3] = v.w;
    }

    float sxv[8];
#pragma unroll
    for (int i = 0; i < 8; i++) sxv[i] = g_sx[rb + w * 8 + i];

    float best[8];
    int   bidx[8];
#pragma unroll
    for (int i = 0; i < 8; i++) { best[i] = FLT_MAX; bidx[i] = 0x7fffffff; }

    const float4* cb4 = reinterpret_cast<const float4*>(cb);

    for (int kb = 0; kb < K; kb += TK) {
        __syncthreads();
        // Stage codebook chunk (TK rows)
        for (int i = tid; i < TK * D4; i += 256) {
            int k = i >> 6, d4 = i & 63;
            float4 v = cb4[(long)(kb + k) * D4 + d4];
            float* p = es + k * STRIDE + d4 * 4;
            p[0] = v.x; p[1] = v.y; p[2] = v.z; p[3] = v.w;
        }
        __syncthreads();

        float acc[8][2];
#pragma unroll
        for (int i = 0; i < 8; i++)
#pragma unroll
            for (int j = 0; j < 2; j++) acc[i][j] = 0.0f;

        const float* xbase = xs + (w * 8) * STRIDE;
        const float* ebase = es + lane * STRIDE;

#pragma unroll 8
        for (int d = 0; d < D; d++) {
            float ev[2], xv[8];
#pragma unroll
            for (int j = 0; j < 2; j++) ev[j] = ebase[j * 32 * STRIDE + d];
#pragma unroll
            for (int i = 0; i < 8; i++) xv[i] = xbase[i * STRIDE + d];
#pragma unroll
            for (int i = 0; i < 8; i++)
#pragma unroll
                for (int j = 0; j < 2; j++)
                    acc[i][j] = fmaf(xv[i], ev[j], acc[i][j]);
        }

        // Finalize this chunk's distances, keep running argmin
#pragma unroll
        for (int j = 0; j < 2; j++) {
            int kg = kb + lane + 32 * j;
            float sev = g_se[kg];
#pragma unroll
            for (int i = 0; i < 8; i++) {
                float t1 = sxv[i] + sev;            // fp32 round (as reference)
                float dd = t1 - 2.0f * acc[i][j];   // 2*m exact, one rounding
                if (dd < best[i] || (dd == best[i] && kg < bidx[i])) {
                    best[i] = dd; bidx[i] = kg;
                }
            }
        }
    }

    // Warp-level argmin reduce per row (lowest-index tie-break)
#pragma unroll
    for (int i = 0; i < 8; i++) {
        float b  = best[i];
        int   bi = bidx[i];
#pragma unroll
        for (int o = 16; o > 0; o >>= 1) {
            float ob  = __shfl_xor_sync(0xFFFFFFFFu, b, o);
            int   obi = __shfl_xor_sync(0xFFFFFFFFu, bi, o);
            if (ob < b || (ob == b && obi < bi)) { b = ob; bi = obi; }
        }
        if (lane == 0) g_idx[rb + w * 8 + i] = bi;
    }
}

// ---------------------------------------------------------------------------
// Gather + straight-through epilogue + index output + histogram.
// One warp per row.
// ---------------------------------------------------------------------------
__global__ void gather_kernel(const float* __restrict__ f,
                              const float* __restrict__ cb,
                              float* __restrict__ out, int N) {
    int row  = blockIdx.x * 8 + (threadIdx.x >> 5);
    int lane = threadIdx.x & 31;
    if (row >= N) return;
    int idx = g_idx[row];

    const float4* q4 = reinterpret_cast<const float4*>(cb) + (long)idx * D4;
    const float4* x4 = reinterpret_cast<const float4*>(f)  + (long)row * D4;
    float4*       o4 = reinterpret_cast<float4*>(out)      + (long)row * D4;

#pragma unroll
    for (int i = 0; i < D4 / 32; i++) {
        float4 q = q4[lane + 32 * i];
        float4 x = x4[lane + 32 * i];
        float4 r;
        // replicate reference: quantized = f + (q - f)  (two fp32 roundings)
        r.x = __fadd_rn(x.x, __fsub_rn(q.x, x.x));
        r.y = __fadd_rn(x.y, __fsub_rn(q.y, x.y));
        r.z = __fadd_rn(x.z, __fsub_rn(q.z, x.z));
        r.w = __fadd_rn(x.w, __fsub_rn(q.w, x.w));
        o4[lane + 32 * i] = r;
    }
    if (lane == 0) {
        out[(long)N * D + 1 + row] = (float)idx;
        atomicAdd(&g_hist[idx], 1);
    }
}

// ---------------------------------------------------------------------------
// Perplexity from histogram. Single block of K threads.
// ---------------------------------------------------------------------------
__global__ void perplexity_kernel(float* __restrict__ out, int N, int K) {
    __shared__ float red[32];
    int k = threadIdx.x;
    float t = 0.0f;
    if (k < K) {
        float p = (float)g_hist[k] * (1.0f / (float)N);
        t = p * logf(p + 1e-10f);
    }
#pragma unroll
    for (int o = 16; o > 0; o >>= 1) t += __shfl_xor_sync(0xFFFFFFFFu, t, o);
    if ((k & 31) == 0) red[k >> 5] = t;
    __syncthreads();
    if (k < 32) {
        int nwarps = (blockDim.x + 31) >> 5;
        float s = (k < nwarps) ? red[k] : 0.0f;
#pragma unroll
        for (int o = 16; o > 0; o >>= 1) s += __shfl_xor_sync(0xFFFFFFFFu, s, o);
        if (k == 0) out[(long)N * D] = expf(-s);
    }
}

// ---------------------------------------------------------------------------
extern "C" void kernel_launch(void* const* d_in, const int* in_sizes, int n_in,
                              void* d_out, int out_size) {
    const float* f  = (const float*)d_in[0];
    const float* cb = (const float*)d_in[1];
    float* out      = (float*)d_out;

    int N = in_sizes[0] / D;   // 65536
    int K = in_sizes[1] / D;   // 1024

    const int smem_bytes = (TM + TK) * STRIDE * (int)sizeof(float);  // ~131 KB
    cudaFuncSetAttribute(argmin_kernel,
                         cudaFuncAttributeMaxDynamicSharedMemorySize, smem_bytes);

    zero_hist_kernel<<<(K + 1023) / 1024, 1024>>>(K);
    rownorm_kernel<<<(N * 32 + 255) / 256, 256>>>(f, N, 0);    // g_sx
    rownorm_kernel<<<(K * 32 + 255) / 256, 256>>>(cb, K, 1);   // g_se
    argmin_kernel<<<N / TM, 256, smem_bytes>>>(f, cb, K);
    gather_kernel<<<(N + 7) / 8, 256>>>(f, cb, out, N);
    perplexity_kernel<<<1, K>>>(out, N, K);
}

// round 7
// speedup vs baseline: 2.0807x; 2.0807x over previous
#include <cuda_runtime.h>
#include <cuda_bf16.h>
#include <math.h>
#include <float.h>
#include <stdint.h>

// ---------------------------------------------------------------------------
// VQ-VAE quantizer via mma.sync bf16 (base-target instructions only).
//   f_emb [N=65536, D=256] fp32, codebook [K=1024, D=256] fp32
// Out (fp32): quantized [N*D] | perplexity [1] | indices [N]
//
// d[n,k] = fl( fl(sx_n+se_k) - 2*dot );  dot via 3-term bf16 split GEMM:
//   virtual A' = [xh | xl | xh] (768), virtual B' = [eh | eh | el] (768)
// stored deduplicated as g_A=[xh|xl] (512), g_B=[eh|el] (512).
// Per-row top-2 kept; exact fp32 rescore picks the final index (zero flips).
// ---------------------------------------------------------------------------

#define D        256
#define NROWS    65536
#define KCODES   1024
#define VPADK    768            // virtual contraction length
#define SPADK    512            // storage stride (deduplicated)
#define MT       128            // CTA M tile
#define NT       256            // CTA N tile
#define KSTAGE   32             // virtual k elems per B stage (2 k16-steps)
#define NSTG     (VPADK / KSTAGE)  // 24
#define SMA_SZ   (MT * VPADK * 2)  // 196608 B (1536 B/row)
#define BSTG_SZ  (NT * KSTAGE * 2) // 16384 B (64 B/row)
#define SMEM_TOT (SMA_SZ + 2 * BSTG_SZ)  // 229376 B

__device__ __nv_bfloat16 g_A[(size_t)NROWS * SPADK];   // 64 MB
__device__ __nv_bfloat16 g_B[(size_t)KCODES * SPADK];  // 1 MB
__device__ float g_sx[NROWS];
__device__ float g_se[KCODES];
__device__ int   g_hist[KCODES];
__device__ int2  g_top2[NROWS];

// ---------------- PTX helpers (sm_80-era, valid on target sm_100) ----------
__device__ __forceinline__ uint32_t smem_u32(const void* p) {
    uint32_t a;
    asm("{ .reg .u64 t; cvta.to.shared.u64 t, %1; cvt.u32.u64 %0, t; }"
        : "=r"(a) : "l"(p));
    return a;
}
__device__ __forceinline__ void cp_async16(uint32_t s, const void* g) {
    asm volatile("cp.async.cg.shared.global [%0], [%1], 16;" :: "r"(s), "l"(g));
}
__device__ __forceinline__ void cp_commit() {
    asm volatile("cp.async.commit_group;" ::: "memory");
}
__device__ __forceinline__ void cp_wait0() {
    asm volatile("cp.async.wait_group 0;" ::: "memory");
}
__device__ __forceinline__ void ldsm4(uint32_t& r0, uint32_t& r1,
                                      uint32_t& r2, uint32_t& r3, uint32_t a) {
    asm volatile("ldmatrix.sync.aligned.m8n8.x4.shared.b16 {%0,%1,%2,%3}, [%4];"
                 : "=r"(r0), "=r"(r1), "=r"(r2), "=r"(r3) : "r"(a));
}
__device__ __forceinline__ void mma16816(float* c, const uint32_t* a,
                                         uint32_t b0, uint32_t b1) {
    asm volatile(
        "mma.sync.aligned.m16n8k16.row.col.f32.bf16.bf16.f32 "
        "{%0,%1,%2,%3}, {%4,%5,%6,%7}, {%8,%9}, {%0,%1,%2,%3};"
        : "+f"(c[0]), "+f"(c[1]), "+f"(c[2]), "+f"(c[3])
        : "r"(a[0]), "r"(a[1]), "r"(a[2]), "r"(a[3]), "r"(b0), "r"(b1));
}
__device__ __forceinline__ bool blt(float d, int i, float d2, int i2) {
    return d < d2 || (d == d2 && i < i2);
}

// ---------------------------------------------------------------------------
__global__ void zero_hist_kernel() {
    g_hist[blockIdx.x * blockDim.x + threadIdx.x] = 0;
}

// g_A row = [xh(256) | xl(256)] bf16 + g_sx. One warp per row.
__global__ void split_f_kernel(const float* __restrict__ f) {
    int row  = blockIdx.x * (blockDim.x >> 5) + (threadIdx.x >> 5);
    int lane = threadIdx.x & 31;
    const float4* f4 = reinterpret_cast<const float4*>(f) + (size_t)row * 64;
    float4 a = f4[lane * 2], b = f4[lane * 2 + 1];
    float x[8] = {a.x, a.y, a.z, a.w, b.x, b.y, b.z, b.w};
    float s = 0.0f;
    uint32_t hi[4], lo[4];
#pragma unroll
    for (int t = 0; t < 4; t++) {
        __nv_bfloat16 h0 = __float2bfloat16_rn(x[2*t]);
        __nv_bfloat16 h1 = __float2bfloat16_rn(x[2*t+1]);
        __nv_bfloat16 l0 = __float2bfloat16_rn(x[2*t]   - __bfloat162float(h0));
        __nv_bfloat16 l1 = __float2bfloat16_rn(x[2*t+1] - __bfloat162float(h1));
        hi[t] = ((uint32_t)__bfloat16_as_ushort(h1) << 16) | __bfloat16_as_ushort(h0);
        lo[t] = ((uint32_t)__bfloat16_as_ushort(l1) << 16) | __bfloat16_as_ushort(l0);
        s += x[2*t]*x[2*t] + x[2*t+1]*x[2*t+1];
    }
    uint4* arow = reinterpret_cast<uint4*>(g_A + (size_t)row * SPADK);
    arow[lane]      = make_uint4(hi[0], hi[1], hi[2], hi[3]);  // xh
    arow[32 + lane] = make_uint4(lo[0], lo[1], lo[2], lo[3]);  // xl
#pragma unroll
    for (int o = 16; o > 0; o >>= 1) s += __shfl_xor_sync(0xFFFFFFFFu, s, o);
    if (lane == 0) g_sx[row] = s;
}

// g_B row = [eh(256) | el(256)] bf16 + g_se. One warp per code.
__global__ void split_cb_kernel(const float* __restrict__ cb) {
    int row  = blockIdx.x * (blockDim.x >> 5) + (threadIdx.x >> 5);
    int lane = threadIdx.x & 31;
    const float4* c4 = reinterpret_cast<const float4*>(cb) + (size_t)row * 64;
    float4 a = c4[lane * 2], b = c4[lane * 2 + 1];
    float x[8] = {a.x, a.y, a.z, a.w, b.x, b.y, b.z, b.w};
    float s = 0.0f;
    uint32_t hi[4], lo[4];
#pragma unroll
    for (int t = 0; t < 4; t++) {
        __nv_bfloat16 h0 = __float2bfloat16_rn(x[2*t]);
        __nv_bfloat16 h1 = __float2bfloat16_rn(x[2*t+1]);
        __nv_bfloat16 l0 = __float2bfloat16_rn(x[2*t]   - __bfloat162float(h0));
        __nv_bfloat16 l1 = __float2bfloat16_rn(x[2*t+1] - __bfloat162float(h1));
        hi[t] = ((uint32_t)__bfloat16_as_ushort(h1) << 16) | __bfloat16_as_ushort(h0);
        lo[t] = ((uint32_t)__bfloat16_as_ushort(l1) << 16) | __bfloat16_as_ushort(l0);
        s += x[2*t]*x[2*t] + x[2*t+1]*x[2*t+1];
    }
    uint4* brow = reinterpret_cast<uint4*>(g_B + (size_t)row * SPADK);
    brow[lane]      = make_uint4(hi[0], hi[1], hi[2], hi[3]);  // eh
    brow[32 + lane] = make_uint4(lo[0], lo[1], lo[2], lo[3]);  // el
#pragma unroll
    for (int o = 16; o > 0; o >>= 1) s += __shfl_xor_sync(0xFFFFFFFFu, s, o);
    if (lane == 0) g_se[row] = s;
}

// ---------------------------------------------------------------------------
// GEMM + fused top-2 argmin.  512 CTAs x 256 threads (8 warps = 2M x 4N),
// warp tile 64x64; virtual-A tile (128x768) resident in smem (built from the
// 512-col storage with chunk remap), B double-buffered.
// ---------------------------------------------------------------------------
extern __shared__ char gsm[];

__global__ __launch_bounds__(256, 1)
void gemm_argmin_kernel() {
    const int tid  = threadIdx.x;
    const int lane = tid & 31;
    const int wid  = tid >> 5;
    const int wm   = wid >> 2;      // 0..1 (M)
    const int wn   = wid & 3;       // 0..3 (N)
    const int rb   = blockIdx.x * MT;

    const uint32_t smA = smem_u32(gsm);
    const uint32_t smB = smA + SMA_SZ;

    // ---- stage virtual-A tile once: 128 rows x 96 chunks of 16B ----
    // virtual chunk c: [0,32)=xh, [32,64)=xl, [64,96)=xh again -> storage c%64
    for (int i = tid; i < MT * 96; i += 256) {
        int r = i / 96, c = i % 96;
        int sc = (c < 64) ? c : c - 64;
        const char* gp = (const char*)(g_A + (size_t)(rb + r) * SPADK + sc * 8);
        cp_async16(smA + r * 1536 + (c ^ (r & 7)) * 16, gp);
    }
    cp_commit();

    // rows this thread owns (slot = 2*ml + h -> row wm*64 + ml*16 + lane/4 + 8h)
    float sxr[8];
#pragma unroll
    for (int ml = 0; ml < 4; ml++) {
        int r0 = wm * 64 + ml * 16 + (lane >> 2);
        sxr[2*ml]   = g_sx[rb + r0];
        sxr[2*ml+1] = g_sx[rb + r0 + 8];
    }

    float bd1[8], bd2[8];
    int   bi1[8], bi2[8];
#pragma unroll
    for (int i = 0; i < 8; i++) {
        bd1[i] = FLT_MAX; bd2[i] = FLT_MAX; bi1[i] = 0x7fffffff; bi2[i] = 0x7fffffff;
    }

    for (int nb = 0; nb < 4; nb++) {
        float acc[4][8][4];
#pragma unroll
        for (int ml = 0; ml < 4; ml++)
#pragma unroll
            for (int na = 0; na < 8; na++)
#pragma unroll
                for (int q = 0; q < 4; q++) acc[ml][na][q] = 0.0f;

        // virtual B chunk vc: [0,32)=eh, [32,64)=eh, [64,96)=el -> storage:
        // vc<32 ? vc : vc-32
        auto loadB = [&](int s, uint32_t dst) {
#pragma unroll
            for (int j = 0; j < 4; j++) {
                int i = tid + j * 256;          // 0..1023
                int n = i >> 2, c = i & 3;      // n row, chunk within stage
                int vc = s * 4 + c;
                int sc = (vc < 32) ? vc : vc - 32;
                int pc = c ^ ((n >> 1) & 3);
                cp_async16(dst + n * 64 + pc * 16,
                           (const char*)(g_B + (size_t)(nb * NT + n) * SPADK + sc * 8));
            }
            cp_commit();
        };

        loadB(0, smB);
        cp_wait0();                 // waits A (first nb) + B stage0
        __syncthreads();

        for (int s = 0; s < NSTG; s++) {
            if (s + 1 < NSTG) loadB(s + 1, smB + ((s + 1) & 1) * BSTG_SZ);
            uint32_t bb = smB + (s & 1) * BSTG_SZ;
#pragma unroll
            for (int k2 = 0; k2 < 2; k2++) {
                int kstep = s * 2 + k2;
                uint32_t a[4][4];
                int ar = wm * 64 + (lane & 15);
                int ac = kstep * 2 + (lane >> 4);
#pragma unroll
                for (int ml = 0; ml < 4; ml++) {
                    int r = ar + ml * 16;
                    ldsm4(a[ml][0], a[ml][1], a[ml][2], a[ml][3],
                          smA + r * 1536 + ((ac ^ (r & 7)) * 16));
                }
#pragma unroll
                for (int np = 0; np < 4; np++) {
                    uint32_t b0, b1, b2, b3;
                    int nr = wn * 64 + np * 16 + (lane & 7) + ((lane >> 4) & 1) * 8;
                    int c  = 2 * k2 + ((lane >> 3) & 1);
                    ldsm4(b0, b1, b2, b3,
                          bb + nr * 64 + ((c ^ ((nr >> 1) & 3)) * 16));
#pragma unroll
                    for (int ml = 0; ml < 4; ml++) {
                        mma16816(acc[ml][2*np],     a[ml], b0, b1);
                        mma16816(acc[ml][2*np + 1], a[ml], b2, b3);
                    }
                }
            }
            cp_wait0();
            __syncthreads();
        }

        // ---- epilogue: d = fl(fl(sx+se) - 2*dot), running top-2 ----
        int cbase = nb * NT + wn * 64;
#pragma unroll
        for (int ml = 0; ml < 4; ml++) {
            float sx0 = sxr[2*ml], sx1 = sxr[2*ml+1];
#pragma unroll
            for (int na = 0; na < 8; na++) {
                int cg = cbase + na * 8 + 2 * (lane & 3);
                float2 se2 = *(reinterpret_cast<const float2*>(g_se) + (cg >> 1));
                float dv[4];
                dv[0] = __fmaf_rn(-2.0f, acc[ml][na][0], __fadd_rn(sx0, se2.x));
                dv[1] = __fmaf_rn(-2.0f, acc[ml][na][1], __fadd_rn(sx0, se2.y));
                dv[2] = __fmaf_rn(-2.0f, acc[ml][na][2], __fadd_rn(sx1, se2.x));
                dv[3] = __fmaf_rn(-2.0f, acc[ml][na][3], __fadd_rn(sx1, se2.y));
#pragma unroll
                for (int q = 0; q < 4; q++) {
                    int slot = 2*ml + (q >> 1);
                    int idx  = cg + (q & 1);
                    float d  = dv[q];
                    if (blt(d, idx, bd1[slot], bi1[slot])) {
                        bd2[slot] = bd1[slot]; bi2[slot] = bi1[slot];
                        bd1[slot] = d;         bi1[slot] = idx;
                    } else if (blt(d, idx, bd2[slot], bi2[slot])) {
                        bd2[slot] = d; bi2[slot] = idx;
                    }
                }
            }
        }
    }

    // ---- intra-quad merge (lanes sharing rows: xor 1, xor 2) ----
#pragma unroll
    for (int slot = 0; slot < 8; slot++) {
#pragma unroll
        for (int off = 1; off <= 2; off <<= 1) {
            float od1 = __shfl_xor_sync(0xFFFFFFFFu, bd1[slot], off);
            int   oi1 = __shfl_xor_sync(0xFFFFFFFFu, bi1[slot], off);
            float od2 = __shfl_xor_sync(0xFFFFFFFFu, bd2[slot], off);
            int   oi2 = __shfl_xor_sync(0xFFFFFFFFu, bi2[slot], off);
            bool f = blt(od1, oi1, bd1[slot], bi1[slot]);
            float w1d = f ? od1 : bd1[slot];  int w1i = f ? oi1 : bi1[slot];
            float l1d = f ? bd1[slot] : od1;  int l1i = f ? bi1[slot] : oi1;
            float c2d = f ? od2 : bd2[slot];  int c2i = f ? oi2 : bi2[slot];
            bool g = blt(c2d, c2i, l1d, l1i);
            bd1[slot] = w1d; bi1[slot] = w1i;
            bd2[slot] = g ? c2d : l1d; bi2[slot] = g ? c2i : l1i;
        }
    }

    // ---- cross-warp merge via smem (reuse B stage area) ----
    __syncthreads();
    float4* mrg = reinterpret_cast<float4*>(gsm + SMA_SZ);
    if ((lane & 3) == 0) {
#pragma unroll
        for (int ml = 0; ml < 4; ml++)
#pragma unroll
            for (int h = 0; h < 2; h++) {
                int slot = 2*ml + h;
                int row = wm * 64 + ml * 16 + (lane >> 2) + h * 8;
                mrg[row * 4 + wn] = make_float4(bd1[slot], __int_as_float(bi1[slot]),
                                                bd2[slot], __int_as_float(bi2[slot]));
            }
    }
    __syncthreads();
    if (tid < MT) {
        float d1 = FLT_MAX, d2 = FLT_MAX; int i1 = 0x7fffffff, i2 = 0x7fffffff;
#pragma unroll
        for (int w = 0; w < 4; w++) {
            float4 v = mrg[tid * 4 + w];
            float od1 = v.x, od2 = v.z;
            int oi1 = __float_as_int(v.y), oi2 = __float_as_int(v.w);
            bool f = blt(od1, oi1, d1, i1);
            float w1d = f ? od1 : d1;  int w1i = f ? oi1 : i1;
            float l1d = f ? d1 : od1;  int l1i = f ? i1 : oi1;
            float c2d = f ? od2 : d2;  int c2i = f ? oi2 : i2;
            bool g = blt(c2d, c2i, l1d, l1i);
            d1 = w1d; i1 = w1i;
            d2 = g ? c2d : l1d; i2 = g ? c2i : l1i;
        }
        g_top2[rb + tid] = make_int2(i1, i2);
    }
}

// ---------------------------------------------------------------------------
// Exact fp32 rescore of top-2 + gather + straight-through + hist + idx out.
// One warp per row.
// ---------------------------------------------------------------------------
__global__ void rescore_gather_kernel(const float* __restrict__ f,
                                      const float* __restrict__ cb,
                                      float* __restrict__ out) {
    int row  = blockIdx.x * (blockDim.x >> 5) + (threadIdx.x >> 5);
    int lane = threadIdx.x & 31;
    int2 cand = g_top2[row];

    const float4* x4  = reinterpret_cast<const float4*>(f)  + (size_t)row * 64;
    const float4* c14 = reinterpret_cast<const float4*>(cb) + (size_t)cand.x * 64;
    const float4* c24 = reinterpret_cast<const float4*>(cb) + (size_t)cand.y * 64;

    float4 xa = x4[lane * 2],   xb = x4[lane * 2 + 1];
    float4 p1a = c14[lane * 2], p1b = c14[lane * 2 + 1];
    float4 p2a = c24[lane * 2], p2b = c24[lane * 2 + 1];

    float sx = xa.x*xa.x + xa.y*xa.y + xa.z*xa.z + xa.w*xa.w
             + xb.x*xb.x + xb.y*xb.y + xb.z*xb.z + xb.w*xb.w;
    float m1 = xa.x*p1a.x + xa.y*p1a.y + xa.z*p1a.z + xa.w*p1a.w
             + xb.x*p1b.x + xb.y*p1b.y + xb.z*p1b.z + xb.w*p1b.w;
    float m2 = xa.x*p2a.x + xa.y*p2a.y + xa.z*p2a.z + xa.w*p2a.w
             + xb.x*p2b.x + xb.y*p2b.y + xb.z*p2b.z + xb.w*p2b.w;
#pragma unroll
    for (int o = 16; o > 0; o >>= 1) {
        sx += __shfl_xor_sync(0xFFFFFFFFu, sx, o);
        m1 += __shfl_xor_sync(0xFFFFFFFFu, m1, o);
        m2 += __shfl_xor_sync(0xFFFFFFFFu, m2, o);
    }
    float d1 = __fmaf_rn(-2.0f, m1, __fadd_rn(sx, g_se[cand.x]));
    float d2 = __fmaf_rn(-2.0f, m2, __fadd_rn(sx, g_se[cand.y]));
    bool first = (d1 < d2) || (d1 == d2 && cand.x < cand.y);
    int win = first ? cand.x : cand.y;

    float4 qa = first ? p1a : p2a;
    float4 qb = first ? p1b : p2b;
    float4 oa, ob;
    oa.x = __fadd_rn(xa.x, __fsub_rn(qa.x, xa.x));
    oa.y = __fadd_rn(xa.y, __fsub_rn(qa.y, xa.y));
    oa.z = __fadd_rn(xa.z, __fsub_rn(qa.z, xa.z));
    oa.w = __fadd_rn(xa.w, __fsub_rn(qa.w, xa.w));
    ob.x = __fadd_rn(xb.x, __fsub_rn(qb.x, xb.x));
    ob.y = __fadd_rn(xb.y, __fsub_rn(qb.y, xb.y));
    ob.z = __fadd_rn(xb.z, __fsub_rn(qb.z, xb.z));
    ob.w = __fadd_rn(xb.w, __fsub_rn(qb.w, xb.w));
    float4* o4 = reinterpret_cast<float4*>(out) + (size_t)row * 64;
    o4[lane * 2]     = oa;
    o4[lane * 2 + 1] = ob;

    if (lane == 0) {
        out[(size_t)NROWS * D + 1 + row] = (float)win;
        atomicAdd(&g_hist[win], 1);
    }
}

// ---------------------------------------------------------------------------
__global__ void perplexity_kernel(float* __restrict__ out) {
    __shared__ float red[32];
    int k = threadIdx.x;
    float p = (float)g_hist[k] * (1.0f / (float)NROWS);
    float t = p * logf(p + 1e-10f);
#pragma unroll
    for (int o = 16; o > 0; o >>= 1) t += __shfl_xor_sync(0xFFFFFFFFu, t, o);
    if ((k & 31) == 0) red[k >> 5] = t;
    __syncthreads();
    if (k < 32) {
        float s = red[k];
#pragma unroll
        for (int o = 16; o > 0; o >>= 1) s += __shfl_xor_sync(0xFFFFFFFFu, s, o);
        if (k == 0) out[(size_t)NROWS * D] = expf(-s);
    }
}

// ---------------------------------------------------------------------------
extern "C" void kernel_launch(void* const* d_in, const int* in_sizes, int n_in,
                              void* d_out, int out_size) {
    const float* f  = (const float*)d_in[0];
    const float* cb = (const float*)d_in[1];
    float* out      = (float*)d_out;

    cudaFuncSetAttribute(gemm_argmin_kernel,
                         cudaFuncAttributeMaxDynamicSharedMemorySize, SMEM_TOT);

    zero_hist_kernel<<<KCODES / 256, 256>>>();
    split_cb_kernel<<<KCODES / 8, 256>>>(cb);
    split_f_kernel<<<NROWS / 8, 256>>>(f);
    gemm_argmin_kernel<<<NROWS / MT, 256, SMEM_TOT>>>();
    rescore_gather_kernel<<<NROWS / 8, 256>>>(f, cb, out);
    perplexity_kernel<<<1, KCODES>>>(out);
}

// round 8
// speedup vs baseline: 3.4495x; 1.6579x over previous
#include <cuda_runtime.h>
#include <cuda_fp16.h>
#include <math.h>
#include <float.h>
#include <stdint.h>

// ---------------------------------------------------------------------------
// VQ-VAE quantizer. Single fp16 GEMM (K=256) for approx distances on the
// tensor pipe; per-thread top-3 -> per-warp-slice top-3 -> global top-4;
// exact fp32 rescore (reference rounding) picks the final index.
//   codebook scaled x1024 into fp16 (avoids fp16 denormals); argmin key in
//   the GEMM is  v = se_k - 2*dot  (sx is row-constant, argmin-invariant).
// ---------------------------------------------------------------------------

#define D        256
#define NROWS    65536
#define KCODES   1024
#define MT       64                 // CTA M tile
#define NT       256                // N tile (codes per pass)
#define ASZ      (MT * 512)         // A tile: 64 rows x 256 fp16 = 32768 B
#define BSTG     16384              // B stage: 256 codes x 32 fp16
#define NBUF     3
#define SMEM_TOT (ASZ + NBUF * BSTG + 1024)   // + align slack
#define ESCALE   (-2.0f / 1024.0f)  // undo codebook x1024, apply -2

__device__ __half g_A[(size_t)NROWS * D];    // 32 MB
__device__ __half g_B[(size_t)KCODES * D];   // 0.5 MB (scaled x1024)
__device__ float  g_se[KCODES];
__device__ int    g_hist[KCODES];
__device__ int4   g_top4[NROWS];

// ---------------- PTX helpers ----------------
__device__ __forceinline__ uint32_t smem_u32(const void* p) {
    uint32_t a;
    asm("{ .reg .u64 t; cvta.to.shared.u64 t, %1; cvt.u32.u64 %0, t; }"
        : "=r"(a) : "l"(p));
    return a;
}
__device__ __forceinline__ void cp_async16(uint32_t s, const void* g) {
    asm volatile("cp.async.cg.shared.global [%0], [%1], 16;" :: "r"(s), "l"(g));
}
__device__ __forceinline__ void cp_commit() {
    asm volatile("cp.async.commit_group;" ::: "memory");
}
__device__ __forceinline__ void cp_wait0() {
    asm volatile("cp.async.wait_group 0;" ::: "memory");
}
__device__ __forceinline__ void cp_wait1() {
    asm volatile("cp.async.wait_group 1;" ::: "memory");
}
__device__ __forceinline__ void ldsm4(uint32_t& r0, uint32_t& r1,
                                      uint32_t& r2, uint32_t& r3, uint32_t a) {
    asm volatile("ldmatrix.sync.aligned.m8n8.x4.shared.b16 {%0,%1,%2,%3}, [%4];"
                 : "=r"(r0), "=r"(r1), "=r"(r2), "=r"(r3) : "r"(a));
}
__device__ __forceinline__ void mma16816(float* c, const uint32_t* a,
                                         uint32_t b0, uint32_t b1) {
    asm volatile(
        "mma.sync.aligned.m16n8k16.row.col.f32.f16.f16.f32 "
        "{%0,%1,%2,%3}, {%4,%5,%6,%7}, {%8,%9}, {%0,%1,%2,%3};"
        : "+f"(c[0]), "+f"(c[1]), "+f"(c[2]), "+f"(c[3])
        : "r"(a[0]), "r"(a[1]), "r"(a[2]), "r"(a[3]), "r"(b0), "r"(b1));
}
__device__ __forceinline__ bool blt(float d, int i, float d2, int i2) {
    return d < d2 || (d == d2 && i < i2);
}
__device__ __forceinline__ void lexmm(float ad, int ai, float bd, int bi,
                                      float& mnd, int& mni, float& mxd, int& mxi) {
    bool f = blt(ad, ai, bd, bi);
    mnd = f ? ad : bd; mni = f ? ai : bi;
    mxd = f ? bd : ad; mxi = f ? bi : ai;
}
__device__ __forceinline__ uint32_t h2u(float x, float y) {
    __half2 h = __floats2half2_rn(x, y);
    return *reinterpret_cast<uint32_t*>(&h);
}

// ---------------------------------------------------------------------------
__global__ void zero_hist_kernel() {
    g_hist[blockIdx.x * blockDim.x + threadIdx.x] = 0;
}

// f -> fp16 row. One warp per row.
__global__ void conv_f_kernel(const float* __restrict__ f) {
    int row  = blockIdx.x * 8 + (threadIdx.x >> 5);
    int lane = threadIdx.x & 31;
    const float4* f4 = reinterpret_cast<const float4*>(f) + (size_t)row * 64;
    float4 a = f4[lane * 2], b = f4[lane * 2 + 1];
    uint4 v = make_uint4(h2u(a.x, a.y), h2u(a.z, a.w), h2u(b.x, b.y), h2u(b.z, b.w));
    reinterpret_cast<uint4*>(g_A + (size_t)row * D)[lane] = v;
}

// cb*1024 -> fp16 row + g_se (exact fp32, from unscaled values).
__global__ void conv_cb_kernel(const float* __restrict__ cb) {
    int row  = blockIdx.x * 8 + (threadIdx.x >> 5);
    int lane = threadIdx.x & 31;
    const float4* c4 = reinterpret_cast<const float4*>(cb) + (size_t)row * 64;
    float4 a = c4[lane * 2], b = c4[lane * 2 + 1];
    float s = a.x*a.x + a.y*a.y + a.z*a.z + a.w*a.w
            + b.x*b.x + b.y*b.y + b.z*b.z + b.w*b.w;
    uint4 v = make_uint4(h2u(a.x * 1024.0f, a.y * 1024.0f),
                         h2u(a.z * 1024.0f, a.w * 1024.0f),
                         h2u(b.x * 1024.0f, b.y * 1024.0f),
                         h2u(b.z * 1024.0f, b.w * 1024.0f));
    reinterpret_cast<uint4*>(g_B + (size_t)row * D)[lane] = v;
#pragma unroll
    for (int o = 16; o > 0; o >>= 1) s += __shfl_xor_sync(0xFFFFFFFFu, s, o);
    if (lane == 0) g_se[row] = s;
}

// ---------------------------------------------------------------------------
// GEMM + top-3 argmin.  1024 CTAs x 256 thr (8 warps = 2M x 4N, warp 32x64),
// A tile resident; B: 3-buffer cp.async ring over 32 flattened stages
// (4 N-tiles x 8 K-stages); epilogue every 8 stages.
// ---------------------------------------------------------------------------
extern __shared__ char gsm_raw[];

__global__ __launch_bounds__(256, 2)
void gemm_argmin_kernel() {
    char* sm = (char*)(((uintptr_t)gsm_raw + 1023) & ~(uintptr_t)1023);
    const int tid  = threadIdx.x;
    const int lane = tid & 31;
    const int wid  = tid >> 5;
    const int wm   = wid >> 2;       // 0..1
    const int wn   = wid & 3;        // 0..3
    const int rb   = blockIdx.x * MT;

    const uint32_t smA = smem_u32(sm);
    const uint32_t smB = smA + ASZ;

    // stage A tile once: 64 rows x 32 chunks of 16B, xor-swizzled
#pragma unroll
    for (int j = 0; j < 8; j++) {
        int i = tid + j * 256;
        int r = i >> 5, c = i & 31;
        cp_async16(smA + r * 512 + ((c ^ (r & 7)) << 4),
                   (const char*)(g_A + (size_t)(rb + r) * D + c * 8));
    }
    cp_commit();

    float acc[2][8][4];
#pragma unroll
    for (int ml = 0; ml < 2; ml++)
#pragma unroll
        for (int na = 0; na < 8; na++)
#pragma unroll
            for (int q = 0; q < 4; q++) acc[ml][na][q] = 0.0f;

    // per-thread top-3 for 4 row-slots (ml 0..1  x  h 0..1)
    float t1d[4], t2d[4], t3d[4];
    int   t1i[4], t2i[4], t3i[4];
#pragma unroll
    for (int s = 0; s < 4; s++) {
        t1d[s] = t2d[s] = t3d[s] = FLT_MAX;
        t1i[s] = t2i[s] = t3i[s] = 0x7fffffff;
    }

    auto loadB = [&](int gs, int buf) {
        int nb = gs >> 3, s = gs & 7;
        uint32_t dst = smB + buf * BSTG;
#pragma unroll
        for (int j = 0; j < 4; j++) {
            int i = tid + j * 256;
            int n = i >> 2, c = i & 3;
            cp_async16(dst + n * 64 + (((c ^ ((n >> 1) & 3)) << 4)),
                       (const char*)(g_B + (size_t)(nb * NT + n) * D + (s * 4 + c) * 8));
        }
        cp_commit();
    };

    loadB(0, 0);
    loadB(1, 1);
    int lbuf = 2, cbuf = 0;   // rotating buffer indices

    for (int gs = 0; gs < 32; gs++) {
        if (gs >= 30) cp_wait0(); else cp_wait1();
        __syncthreads();
        if (gs + 2 < 32) {
            loadB(gs + 2, lbuf);
            if (++lbuf == NBUF) lbuf = 0;
        }

        uint32_t bb = smB + cbuf * BSTG;
        if (++cbuf == NBUF) cbuf = 0;
#pragma unroll
        for (int k2 = 0; k2 < 2; k2++) {
            int t = (gs & 7) * 2 + k2;           // kstep 0..15
            uint32_t a[2][4];
            int ar = wm * 32 + (lane & 15);
            int ac = t * 2 + (lane >> 4);
#pragma unroll
            for (int ml = 0; ml < 2; ml++) {
                int r = ar + ml * 16;
                ldsm4(a[ml][0], a[ml][1], a[ml][2], a[ml][3],
                      smA + r * 512 + (((ac ^ (r & 7)) << 4)));
            }
#pragma unroll
            for (int np = 0; np < 4; np++) {
                uint32_t b0, b1, b2, b3;
                int nr = wn * 64 + np * 16 + (lane & 7) + ((lane >> 4) & 1) * 8;
                int c  = 2 * k2 + ((lane >> 3) & 1);
                ldsm4(b0, b1, b2, b3,
                      bb + nr * 64 + (((c ^ ((nr >> 1) & 3)) << 4)));
#pragma unroll
                for (int ml = 0; ml < 2; ml++) {
                    mma16816(acc[ml][2 * np],     a[ml], b0, b1);
                    mma16816(acc[ml][2 * np + 1], a[ml], b2, b3);
                }
            }
        }

        if ((gs & 7) == 7) {
            // epilogue for N-tile nb: key v = se - (2/1024)*dot', top-3 insert
            int nb = gs >> 3;
            int cbase = nb * NT + wn * 64;
#pragma unroll
            for (int ml = 0; ml < 2; ml++) {
#pragma unroll
                for (int na = 0; na < 8; na++) {
                    int cg = cbase + na * 8 + 2 * (lane & 3);
                    float2 se2 = *(reinterpret_cast<const float2*>(g_se) + (cg >> 1));
                    float dv[4];
                    dv[0] = __fmaf_rn(ESCALE, acc[ml][na][0], se2.x);
                    dv[1] = __fmaf_rn(ESCALE, acc[ml][na][1], se2.y);
                    dv[2] = __fmaf_rn(ESCALE, acc[ml][na][2], se2.x);
                    dv[3] = __fmaf_rn(ESCALE, acc[ml][na][3], se2.y);
#pragma unroll
                    for (int q = 0; q < 4; q++) {
                        int s  = 2 * ml + (q >> 1);
                        int ix = cg + (q & 1);
                        float d = dv[q];
                        if (blt(d, ix, t3d[s], t3i[s])) {
                            if (blt(d, ix, t1d[s], t1i[s])) {
                                t3d[s]=t2d[s]; t3i[s]=t2i[s];
                                t2d[s]=t1d[s]; t2i[s]=t1i[s];
                                t1d[s]=d;      t1i[s]=ix;
                            } else if (blt(d, ix, t2d[s], t2i[s])) {
                                t3d[s]=t2d[s]; t3i[s]=t2i[s];
                                t2d[s]=d;      t2i[s]=ix;
                            } else {
                                t3d[s]=d;      t3i[s]=ix;
                            }
                        }
                        acc[ml][na][q] = 0.0f;   // reset for next N-tile
                    }
                }
            }
        }
    }

    // ---- intra-quad merge of sorted triples (lanes xor 1, xor 2) ----
#pragma unroll
    for (int s = 0; s < 4; s++) {
#pragma unroll
        for (int off = 1; off <= 2; off <<= 1) {
            float e1d = __shfl_xor_sync(0xFFFFFFFFu, t1d[s], off);
            int   e1i = __shfl_xor_sync(0xFFFFFFFFu, t1i[s], off);
            float e2d = __shfl_xor_sync(0xFFFFFFFFu, t2d[s], off);
            int   e2i = __shfl_xor_sync(0xFFFFFFFFu, t2i[s], off);
            float e3d = __shfl_xor_sync(0xFFFFFFFFu, t3d[s], off);
            int   e3i = __shfl_xor_sync(0xFFFFFFFFu, t3i[s], off);
            float x1d, y1d, x2d, y2d, x3d, dum; int x1i, y1i, x2i, y2i, x3i, dmi;
            lexmm(t1d[s], t1i[s], e1d, e1i, x1d, x1i, y1d, y1i);
            lexmm(t2d[s], t2i[s], e2d, e2i, x2d, x2i, y2d, y2i);
            lexmm(t3d[s], t3i[s], e3d, e3i, x3d, x3i, dum, dmi);
            // r1=x1; r2=min(y1,x2); r3=min(max(y1,x2), x3)
            t1d[s] = x1d; t1i[s] = x1i;
            float m1d, m2d; int m1i, m2i;
            lexmm(y1d, y1i, x2d, x2i, m1d, m1i, m2d, m2i);
            t2d[s] = m1d; t2i[s] = m1i;
            bool g = blt(m2d, m2i, x3d, x3i);
            t3d[s] = g ? m2d : x3d; t3i[s] = g ? m2i : x3i;
        }
    }

    // ---- cross-warp: stash per-(row, wn) top-3, then global top-4 ----
    __syncthreads();
    float4* mrg = reinterpret_cast<float4*>(sm + ASZ);   // reuse B ring
    if ((lane & 3) == 0) {
#pragma unroll
        for (int s = 0; s < 4; s++) {
            int row = wm * 32 + (s >> 1) * 16 + (lane >> 2) + (s & 1) * 8;
            mrg[(row * 4 + wn) * 2]     = make_float4(t1d[s], __int_as_float(t1i[s]),
                                                      t2d[s], __int_as_float(t2i[s]));
            mrg[(row * 4 + wn) * 2 + 1] = make_float4(t3d[s], __int_as_float(t3i[s]),
                                                      FLT_MAX, __int_as_float(0x7fffffff));
        }
    }
    __syncthreads();
    if (tid < MT) {
        float cd[12]; int ci[12];
#pragma unroll
        for (int w = 0; w < 4; w++) {
            float4 u = mrg[(tid * 4 + w) * 2];
            float4 v = mrg[(tid * 4 + w) * 2 + 1];
            cd[w*3]   = u.x; ci[w*3]   = __float_as_int(u.y);
            cd[w*3+1] = u.z; ci[w*3+1] = __float_as_int(u.w);
            cd[w*3+2] = v.x; ci[w*3+2] = __float_as_int(v.y);
        }
#pragma unroll
        for (int a = 0; a < 4; a++)
#pragma unroll
            for (int t = 11; t > a; t--)
                if (blt(cd[t], ci[t], cd[t-1], ci[t-1])) {
                    float td = cd[t]; cd[t] = cd[t-1]; cd[t-1] = td;
                    int   ti = ci[t]; ci[t] = ci[t-1]; ci[t-1] = ti;
                }
        g_top4[rb + tid] = make_int4(ci[0], ci[1], ci[2], ci[3]);
    }
}

// ---------------------------------------------------------------------------
// Exact fp32 rescore of 4 candidates (reference rounding structure) + gather
// + straight-through + hist + idx.  One warp per row.
// ---------------------------------------------------------------------------
__global__ void rescore_gather_kernel(const float* __restrict__ f,
                                      const float* __restrict__ cb,
                                      float* __restrict__ out) {
    int row  = blockIdx.x * 8 + (threadIdx.x >> 5);
    int lane = threadIdx.x & 31;
    int4 cd = g_top4[row];

    const float4* x4 = reinterpret_cast<const float4*>(f) + (size_t)row * 64;
    float4 xa = x4[lane * 2], xb = x4[lane * 2 + 1];
    float sx = xa.x*xa.x + xa.y*xa.y + xa.z*xa.z + xa.w*xa.w
             + xb.x*xb.x + xb.y*xb.y + xb.z*xb.z + xb.w*xb.w;

    int cix[4] = {cd.x, cd.y, cd.z, cd.w};
    float4 pa[4], pb[4];
    float m[4];
#pragma unroll
    for (int j = 0; j < 4; j++) {
        const float4* c4 = reinterpret_cast<const float4*>(cb) + (size_t)cix[j] * 64;
        pa[j] = c4[lane * 2]; pb[j] = c4[lane * 2 + 1];
        m[j] = xa.x*pa[j].x + xa.y*pa[j].y + xa.z*pa[j].z + xa.w*pa[j].w
             + xb.x*pb[j].x + xb.y*pb[j].y + xb.z*pb[j].z + xb.w*pb[j].w;
    }
#pragma unroll
    for (int o = 16; o > 0; o >>= 1) {
        sx   += __shfl_xor_sync(0xFFFFFFFFu, sx,   o);
        m[0] += __shfl_xor_sync(0xFFFFFFFFu, m[0], o);
        m[1] += __shfl_xor_sync(0xFFFFFFFFu, m[1], o);
        m[2] += __shfl_xor_sync(0xFFFFFFFFu, m[2], o);
        m[3] += __shfl_xor_sync(0xFFFFFFFFu, m[3], o);
    }
    float bd = FLT_MAX; int bi = 0x7fffffff;
    float4 qa = pa[0], qb = pb[0];
#pragma unroll
    for (int j = 0; j < 4; j++) {
        float dj = __fmaf_rn(-2.0f, m[j], __fadd_rn(sx, g_se[cix[j]]));
        if (blt(dj, cix[j], bd, bi)) { bd = dj; bi = cix[j]; qa = pa[j]; qb = pb[j]; }
    }

    float4 oa, ob;
    oa.x = __fadd_rn(xa.x, __fsub_rn(qa.x, xa.x));
    oa.y = __fadd_rn(xa.y, __fsub_rn(qa.y, xa.y));
    oa.z = __fadd_rn(xa.z, __fsub_rn(qa.z, xa.z));
    oa.w = __fadd_rn(xa.w, __fsub_rn(qa.w, xa.w));
    ob.x = __fadd_rn(xb.x, __fsub_rn(qb.x, xb.x));
    ob.y = __fadd_rn(xb.y, __fsub_rn(qb.y, xb.y));
    ob.z = __fadd_rn(xb.z, __fsub_rn(qb.z, xb.z));
    ob.w = __fadd_rn(xb.w, __fsub_rn(qb.w, xb.w));
    float4* o4 = reinterpret_cast<float4*>(out) + (size_t)row * 64;
    o4[lane * 2]     = oa;
    o4[lane * 2 + 1] = ob;

    if (lane == 0) {
        out[(size_t)NROWS * D + 1 + row] = (float)bi;
        atomicAdd(&g_hist[bi], 1);
    }
}

// ---------------------------------------------------------------------------
__global__ void perplexity_kernel(float* __restrict__ out) {
    __shared__ float red[32];
    int k = threadIdx.x;
    float p = (float)g_hist[k] * (1.0f / (float)NROWS);
    float t = p * logf(p + 1e-10f);
#pragma unroll
    for (int o = 16; o > 0; o >>= 1) t += __shfl_xor_sync(0xFFFFFFFFu, t, o);
    if ((k & 31) == 0) red[k >> 5] = t;
    __syncthreads();
    if (k < 32) {
        float s = red[k];
#pragma unroll
        for (int o = 16; o > 0; o >>= 1) s += __shfl_xor_sync(0xFFFFFFFFu, s, o);
        if (k == 0) out[(size_t)NROWS * D] = expf(-s);
    }
}

// ---------------------------------------------------------------------------
extern "C" void kernel_launch(void* const* d_in, const int* in_sizes, int n_in,
                              void* d_out, int out_size) {
    const float* f  = (const float*)d_in[0];
    const float* cb = (const float*)d_in[1];
    float* out      = (float*)d_out;

    cudaFuncSetAttribute(gemm_argmin_kernel,
                         cudaFuncAttributeMaxDynamicSharedMemorySize, SMEM_TOT);

    zero_hist_kernel<<<KCODES / 256, 256>>>();
    conv_cb_kernel<<<KCODES / 8, 256>>>(cb);
    conv_f_kernel<<<NROWS / 8, 256>>>(f);
    gemm_argmin_kernel<<<NROWS / MT, 256, SMEM_TOT>>>();
    rescore_gather_kernel<<<NROWS / 8, 256>>>(f, cb, out);
    perplexity_kernel<<<1, KCODES>>>(out);
}